// round 3
// baseline (speedup 1.0000x reference)
#include <cuda_runtime.h>
#include <cuda_bf16.h>

#define POS_WEIGHT 1.0f
#define NEG_WEIGHT 8.0f
#define EPS 1e-7f

#define NBLK   1184      // 148 SMs * 8 resident blocks @ 256 thr, 32 regs
#define NTH    256
#define CHUNK  512       // float4 elements per chunk (8KB x + 8KB t)
#define MAXCHUNK 16384   // n4 / CHUNK for N = 2^25

__device__ float        g_chunk_sums[MAXCHUNK];
__device__ unsigned int g_work  = 0;   // chunk dispenser (self-resetting)
__device__ unsigned int g_count = 0;   // completion gate (self-resetting)

__device__ __forceinline__ void bce_elem(float x, int t, float& sum) {
    bool  pos = (t == 1);
    float arg = pos ? (x + EPS) : ((1.0f - x) + EPS);
    float w   = pos ? POS_WEIGHT : NEG_WEIGHT;
    sum = fmaf(-w, __logf(arg), sum);
}

__device__ __forceinline__ void bce_vec4(const float4 xv, const int4 tv, float& sum) {
    bce_elem(xv.x, tv.x, sum);
    bce_elem(xv.y, tv.y, sum);
    bce_elem(xv.z, tv.z, sum);
    bce_elem(xv.w, tv.w, sum);
}

__global__ __launch_bounds__(NTH, 8) void bce_dyn_kernel(
    const float4* __restrict__ x4,
    const int4*   __restrict__ t4,
    int nchunk,
    float* __restrict__ out,
    float inv_n)
{
    __shared__ float        warp_sums[NTH / 32];
    __shared__ unsigned int s_next;
    __shared__ bool         s_last;

    const int lane = threadIdx.x & 31;
    const int wid  = threadIdx.x >> 5;

    if (threadIdx.x == 0)
        s_next = atomicAdd(&g_work, 1u);
    __syncthreads();
    unsigned int chunk = s_next;

    while (chunk < (unsigned)nchunk) {
        const int base = chunk * CHUNK + threadIdx.x;

        // 4 independent 128B streaming loads, front-batched
        float4 xa = __ldcs(&x4[base]);
        int4   ta = __ldcs(&t4[base]);
        float4 xb = __ldcs(&x4[base + NTH]);
        int4   tb = __ldcs(&t4[base + NTH]);

        // Grab next chunk while loads are in flight (hides atomic latency)
        if (threadIdx.x == 0)
            s_next = atomicAdd(&g_work, 1u);

        float s = 0.0f;
        bce_vec4(xa, ta, s);
        bce_vec4(xb, tb, s);

        #pragma unroll
        for (int o = 16; o > 0; o >>= 1)
            s += __shfl_xor_sync(0xffffffffu, s, o);
        if (lane == 0)
            warp_sums[wid] = s;
        __syncthreads();                     // warp_sums + s_next visible

        if (threadIdx.x == 0) {
            float v = 0.0f;
            #pragma unroll
            for (int w = 0; w < NTH / 32; w++)
                v += warp_sums[w];
            g_chunk_sums[chunk] = v;         // value independent of which block ran it
        }
        unsigned int next = s_next;          // everyone reads before bar2
        __syncthreads();                     // protect warp_sums/s_next reuse
        chunk = next;
    }

    // Completion gate
    if (threadIdx.x == 0) {
        __threadfence();                     // publish chunk sums
        unsigned int prev = atomicAdd(&g_count, 1u);
        s_last = (prev == NBLK - 1);
    }
    __syncthreads();

    // Last block: fixed-order reduction over chunk sums -> bitwise deterministic
    if (s_last) {
        __threadfence();
        const float4* cs4 = (const float4*)g_chunk_sums;
        const int n4s = nchunk / 4;          // 4096
        float v = 0.0f;
        for (int j = threadIdx.x; j < n4s; j += NTH) {
            float4 c = cs4[j];
            v += (c.x + c.y) + (c.z + c.w);
        }
        #pragma unroll
        for (int o = 16; o > 0; o >>= 1)
            v += __shfl_xor_sync(0xffffffffu, v, o);
        if (lane == 0)
            warp_sums[wid] = v;
        __syncthreads();
        if (threadIdx.x == 0) {
            float tot = 0.0f;
            #pragma unroll
            for (int w = 0; w < NTH / 32; w++)
                tot += warp_sums[w];
            out[0]  = tot * inv_n;
            g_work  = 0;                     // reset for next graph replay
            g_count = 0;
        }
    }
}

extern "C" void kernel_launch(void* const* d_in, const int* in_sizes, int n_in,
                              void* d_out, int out_size)
{
    const float* outputs = (const float*)d_in[0];
    const int*   targets = (const int*)d_in[1];
    float*       out     = (float*)d_out;

    const int n      = in_sizes[0];          // 33554432
    const int n4     = n / 4;                // 8388608
    const int nchunk = n4 / CHUNK;           // 16384, exact

    bce_dyn_kernel<<<NBLK, NTH>>>(
        (const float4*)outputs, (const int4*)targets, nchunk, out, 1.0f / (float)n);
}

// round 6
// speedup vs baseline: 1.0483x; 1.0483x over previous
#include <cuda_runtime.h>
#include <cuda_bf16.h>

#define POS_WEIGHT 1.0f
#define NEG_WEIGHT 8.0f
#define EPS 1e-7f

#define NBLK 740       // 148 SMs * 5 resident blocks (regs ~48 @ unroll x4)
#define NTH  256

__device__ float        g_partials[NBLK];
__device__ unsigned int g_count = 0;   // self-resetting gate (graph-replay safe)

__device__ __forceinline__ void bce_elem(float x, int t, float& sum) {
    bool  pos = (t == 1);
    float arg = pos ? (x + EPS) : ((1.0f - x) + EPS);
    float w   = pos ? POS_WEIGHT : NEG_WEIGHT;
    sum = fmaf(-w, __logf(arg), sum);
}

__device__ __forceinline__ void bce_vec4(const float4 xv, const int4 tv, float& sum) {
    bce_elem(xv.x, tv.x, sum);
    bce_elem(xv.y, tv.y, sum);
    bce_elem(xv.z, tv.z, sum);
    bce_elem(xv.w, tv.w, sum);
}

__global__ __launch_bounds__(NTH) void bce_fused_kernel(
    const float4* __restrict__ x4,
    const int4*   __restrict__ t4,
    int n4,
    float* __restrict__ out,
    float inv_n)
{
    const int tid    = blockIdx.x * NTH + threadIdx.x;
    const int stride = NBLK * NTH;

    float sum0 = 0.0f, sum1 = 0.0f, sum2 = 0.0f, sum3 = 0.0f;

    // Grid-stride, unrolled x4: 8 independent 128B streaming loads
    // front-batched per warp -> 2x the in-flight bytes of the x2 version.
    int i = tid;
    for (; i + 3 * stride < n4; i += 4 * stride) {
        float4 xa = __ldcs(&x4[i]);
        int4   ta = __ldcs(&t4[i]);
        float4 xb = __ldcs(&x4[i + stride]);
        int4   tb = __ldcs(&t4[i + stride]);
        float4 xc = __ldcs(&x4[i + 2 * stride]);
        int4   tc = __ldcs(&t4[i + 2 * stride]);
        float4 xd = __ldcs(&x4[i + 3 * stride]);
        int4   td = __ldcs(&t4[i + 3 * stride]);
        bce_vec4(xa, ta, sum0);
        bce_vec4(xb, tb, sum1);
        bce_vec4(xc, tc, sum2);
        bce_vec4(xd, td, sum3);
    }
    for (; i < n4; i += stride) {
        float4 xa = __ldcs(&x4[i]);
        int4   ta = __ldcs(&t4[i]);
        bce_vec4(xa, ta, sum0);
    }

    float sum = (sum0 + sum1) + (sum2 + sum3);

    // Warp reduce
    #pragma unroll
    for (int o = 16; o > 0; o >>= 1)
        sum += __shfl_xor_sync(0xffffffffu, sum, o);

    __shared__ float warp_sums[NTH / 32];
    __shared__ bool  s_is_last;

    if ((threadIdx.x & 31) == 0)
        warp_sums[threadIdx.x >> 5] = sum;
    __syncthreads();

    if (threadIdx.x == 0) {
        float v = 0.0f;
        #pragma unroll
        for (int w = 0; w < NTH / 32; w++)
            v += warp_sums[w];
        g_partials[blockIdx.x] = v;        // deterministic per-block partial
        __threadfence();
        unsigned int prev = atomicAdd(&g_count, 1u);
        s_is_last = (prev == NBLK - 1);
    }
    __syncthreads();

    // Last-arriving block: fixed-order reduction -> bitwise deterministic.
    if (s_is_last) {
        __threadfence();
        float v = 0.0f;
        for (int j = threadIdx.x; j < NBLK; j += NTH)
            v += g_partials[j];
        #pragma unroll
        for (int o = 16; o > 0; o >>= 1)
            v += __shfl_xor_sync(0xffffffffu, v, o);
        if ((threadIdx.x & 31) == 0)
            warp_sums[threadIdx.x >> 5] = v;
        __syncthreads();
        if (threadIdx.x == 0) {
            float tot = 0.0f;
            #pragma unroll
            for (int w = 0; w < NTH / 32; w++)
                tot += warp_sums[w];
            out[0]  = tot * inv_n;
            g_count = 0;                   // reset gate for next graph replay
        }
    }
}

extern "C" void kernel_launch(void* const* d_in, const int* in_sizes, int n_in,
                              void* d_out, int out_size)
{
    const float* outputs = (const float*)d_in[0];
    const int*   targets = (const int*)d_in[1];
    float*       out     = (float*)d_out;

    const int n  = in_sizes[0];        // 33554432
    const int n4 = n / 4;              // 8388608

    bce_fused_kernel<<<NBLK, NTH>>>(
        (const float4*)outputs, (const int4*)targets, n4, out, 1.0f / (float)n);
}